// round 1
// baseline (speedup 1.0000x reference)
#include <cuda_runtime.h>

#define BATCH 8
#define HEADS 8
#define NSEQ  4096
#define DM    512
#define DH    64
#define RP    256

// ---------------- scratch (static device globals; no allocations) ----------------
__device__ float g_Q [BATCH*HEADS*NSEQ*DH];   // 64 MB  [b,h,n,dh]
__device__ float g_K [BATCH*HEADS*NSEQ*DH];   // 64 MB
__device__ float g_V [BATCH*HEADS*NSEQ*DH];   // 64 MB
__device__ float g_KP[BATCH*HEADS*RP*DH];     // 512 KB [b,h,r,dh]
__device__ float g_VP[BATCH*HEADS*RP*DH];     // 512 KB
__device__ float g_AO[BATCH*NSEQ*DM];         // 64 MB  [b,n,h*dh]

// =====================================================================
// Kernel 1: QKV projection.  C[m,c] = sum_k x[m,k] * w[k,c]
// grid (4, 256, 3): 128x128 output tiles, z selects {wq,wk,wv}.
// Output written head-split: [b,h,n,64].
// =====================================================================
__global__ __launch_bounds__(256) void qkv_kernel(
    const float* __restrict__ x, const float* __restrict__ wq,
    const float* __restrict__ wk, const float* __restrict__ wv)
{
    __shared__ float As[16][128];
    __shared__ float Bs[16][128];

    const float* w; float* outp;
    if (blockIdx.z == 0)      { w = wq; outp = g_Q; }
    else if (blockIdx.z == 1) { w = wk; outp = g_K; }
    else                      { w = wv; outp = g_V; }

    const int m0 = blockIdx.y * 128;
    const int n0 = blockIdx.x * 128;
    const int tid = threadIdx.x;
    const int tx = tid & 15, ty = tid >> 4;

    float acc[8][8];
    #pragma unroll
    for (int i = 0; i < 8; i++)
        #pragma unroll
        for (int j = 0; j < 8; j++) acc[i][j] = 0.f;

    for (int k0 = 0; k0 < DM; k0 += 16) {
        #pragma unroll
        for (int l = 0; l < 2; l++) {
            int s = l * 256 + tid;
            int row = s >> 2, kq = (s & 3) * 4;
            float4 v = *(const float4*)&x[(m0 + row) * DM + k0 + kq];
            As[kq + 0][row] = v.x; As[kq + 1][row] = v.y;
            As[kq + 2][row] = v.z; As[kq + 3][row] = v.w;
        }
        #pragma unroll
        for (int l = 0; l < 2; l++) {
            int s = l * 256 + tid;
            int row = s >> 5, cq = (s & 31) * 4;
            *(float4*)&Bs[row][cq] = *(const float4*)&w[(k0 + row) * DM + n0 + cq];
        }
        __syncthreads();
        #pragma unroll
        for (int kk = 0; kk < 16; kk++) {
            float a[8], b[8];
            *(float4*)&a[0] = *(float4*)&As[kk][ty * 8];
            *(float4*)&a[4] = *(float4*)&As[kk][ty * 8 + 4];
            *(float4*)&b[0] = *(float4*)&Bs[kk][tx * 8];
            *(float4*)&b[4] = *(float4*)&Bs[kk][tx * 8 + 4];
            #pragma unroll
            for (int i = 0; i < 8; i++)
                #pragma unroll
                for (int j = 0; j < 8; j++)
                    acc[i][j] = fmaf(a[i], b[j], acc[i][j]);
        }
        __syncthreads();
    }

    #pragma unroll
    for (int i = 0; i < 8; i++) {
        int m = m0 + ty * 8 + i;
        int bb = m >> 12, ns = m & (NSEQ - 1);
        #pragma unroll
        for (int j = 0; j < 8; j += 4) {
            int c = n0 + tx * 8 + j;
            int h = c >> 6, dh = c & 63;
            float4 v = make_float4(acc[i][j], acc[i][j+1], acc[i][j+2], acc[i][j+3]);
            *(float4*)&outp[(((bb * HEADS + h) * NSEQ + ns) * DH) + dh] = v;
        }
    }
}

// =====================================================================
// Kernel 2: low-rank projection.  KP[b,h,r,d] = sum_n E[h,n,r]*K[b,h,n,d]
// grid (2, 64, 2): x = 128-row r block, y = (b,h), z = {E->KP, F->VP}
// =====================================================================
__global__ __launch_bounds__(256) void proj_kernel(
    const float* __restrict__ E, const float* __restrict__ F)
{
    __shared__ float Es[16][128];
    __shared__ float Ks[16][64];

    const int bh = blockIdx.y;
    const int h = bh & 7;
    const int r0 = blockIdx.x * 128;
    const float* P = (blockIdx.z == 0 ? E : F) + h * NSEQ * RP;      // [4096,256]
    const float* S = (blockIdx.z == 0 ? g_K : g_V) + bh * NSEQ * DH; // [4096,64]
    float*       D = (blockIdx.z == 0 ? g_KP : g_VP) + bh * RP * DH;

    const int tid = threadIdx.x;
    const int tx = tid & 15, ty = tid >> 4;

    float acc[8][4];
    #pragma unroll
    for (int i = 0; i < 8; i++)
        #pragma unroll
        for (int j = 0; j < 4; j++) acc[i][j] = 0.f;

    for (int k0 = 0; k0 < NSEQ; k0 += 16) {
        #pragma unroll
        for (int l = 0; l < 2; l++) {
            int s = l * 256 + tid;
            int row = s >> 5, cq = (s & 31) * 4;
            *(float4*)&Es[row][cq] = *(const float4*)&P[(k0 + row) * RP + r0 + cq];
        }
        {
            int row = tid >> 4, cq = (tid & 15) * 4;
            *(float4*)&Ks[row][cq] = *(const float4*)&S[(k0 + row) * DH + cq];
        }
        __syncthreads();
        #pragma unroll
        for (int kk = 0; kk < 16; kk++) {
            float a[8], b[4];
            *(float4*)&a[0] = *(float4*)&Es[kk][ty * 8];
            *(float4*)&a[4] = *(float4*)&Es[kk][ty * 8 + 4];
            *(float4*)&b[0] = *(float4*)&Ks[kk][tx * 4];
            #pragma unroll
            for (int i = 0; i < 8; i++)
                #pragma unroll
                for (int j = 0; j < 4; j++)
                    acc[i][j] = fmaf(a[i], b[j], acc[i][j]);
        }
        __syncthreads();
    }

    #pragma unroll
    for (int i = 0; i < 8; i++) {
        float4 v = make_float4(acc[i][0], acc[i][1], acc[i][2], acc[i][3]);
        *(float4*)&D[(r0 + ty * 8 + i) * DH + tx * 4] = v;
    }
}

// =====================================================================
// Kernel 3: fused attention per (b,h, 64-row Q block).
//   S = Q_blk @ kp^T  (64x256, K=64)  -> softmax rows -> O = P @ vp (64x64)
// Scores never touch gmem.  Dynamic smem: Qs + kpT + vps + Ps = 210 KB.
// grid (64, 64): x = q block, y = (b,h).  256 threads.
// =====================================================================
#define ATTN_SMEM_FLOATS (64*68 + 64*256 + 256*64 + 64*260)
#define ATTN_SMEM_BYTES  (ATTN_SMEM_FLOATS * 4)

__global__ __launch_bounds__(256) void attn_kernel()
{
    extern __shared__ float sm[];
    float* Qs  = sm;                  // [64][68]  padded
    float* kpT = Qs + 64 * 68;        // [64][256] d-major (kpT[d][r])
    float* vps = kpT + 64 * 256;      // [256][64]
    float* Ps  = vps + 256 * 64;      // [64][260] padded

    const int bh = blockIdx.y;
    const int n0 = blockIdx.x * 64;
    const float* Qg = g_Q + (bh * NSEQ + n0) * DH;
    const float* kp = g_KP + bh * RP * DH;
    const float* vp = g_VP + bh * RP * DH;

    const int tid = threadIdx.x;
    const int tx = tid & 15, ty = tid >> 4;

    // ---- stage loads ----
    #pragma unroll
    for (int l = 0; l < 4; l++) {                 // Q: 64x64
        int s = l * 256 + tid;
        int i = s >> 4, dq = (s & 15) * 4;
        *(float4*)&Qs[i * 68 + dq] = *(const float4*)&Qg[i * DH + dq];
    }
    #pragma unroll
    for (int l = 0; l < 16; l++) {                // kp transpose: [256][64] -> [64][256]
        int s = l * 256 + tid;
        int r = s >> 4, dq = (s & 15) * 4;
        float4 v = *(const float4*)&kp[r * DH + dq];
        kpT[(dq + 0) * RP + r] = v.x; kpT[(dq + 1) * RP + r] = v.y;
        kpT[(dq + 2) * RP + r] = v.z; kpT[(dq + 3) * RP + r] = v.w;
    }
    #pragma unroll
    for (int l = 0; l < 16; l++) {                // vp copy
        int s = l * 256 + tid;
        int r = s >> 4, dq = (s & 15) * 4;
        *(float4*)&vps[r * DH + dq] = *(const float4*)&vp[r * DH + dq];
    }
    __syncthreads();

    // ---- phase 1: S = Q @ kp^T, thread tile = 4 rows x 16 cols ----
    float acc[4][16];
    #pragma unroll
    for (int i = 0; i < 4; i++)
        #pragma unroll
        for (int c = 0; c < 16; c++) acc[i][c] = 0.f;

    #pragma unroll 4
    for (int d = 0; d < DH; d++) {
        float q[4];
        #pragma unroll
        for (int i = 0; i < 4; i++) q[i] = Qs[(ty * 4 + i) * 68 + d];
        float kr[16];
        #pragma unroll
        for (int c4 = 0; c4 < 16; c4 += 4)
            *(float4*)&kr[c4] = *(float4*)&kpT[d * RP + tx * 16 + c4];
        #pragma unroll
        for (int i = 0; i < 4; i++)
            #pragma unroll
            for (int c = 0; c < 16; c++)
                acc[i][c] = fmaf(q[i], kr[c], acc[i][c]);
    }

    // ---- softmax over r (16 cols/thread, reduce across the 16-lane tx group) ----
    const float scale = 0.125f;  // 1/sqrt(64)
    #pragma unroll
    for (int i = 0; i < 4; i++) {
        float m = acc[i][0];
        #pragma unroll
        for (int c = 1; c < 16; c++) m = fmaxf(m, acc[i][c]);
        #pragma unroll
        for (int off = 8; off > 0; off >>= 1)
            m = fmaxf(m, __shfl_xor_sync(0xffffffffu, m, off, 16));
        float sum = 0.f;
        #pragma unroll
        for (int c = 0; c < 16; c++) {
            float p = __expf((acc[i][c] - m) * scale);
            acc[i][c] = p;
            sum += p;
        }
        #pragma unroll
        for (int off = 8; off > 0; off >>= 1)
            sum += __shfl_xor_sync(0xffffffffu, sum, off, 16);
        float inv = __frcp_rn(sum);
        #pragma unroll
        for (int c4 = 0; c4 < 16; c4 += 4) {
            float4 v = make_float4(acc[i][c4] * inv, acc[i][c4+1] * inv,
                                   acc[i][c4+2] * inv, acc[i][c4+3] * inv);
            *(float4*)&Ps[(ty * 4 + i) * 260 + tx * 16 + c4] = v;
        }
    }
    __syncthreads();

    // ---- phase 2: O = P @ vp, thread tile = 4 rows x 4 cols ----
    float o[4][4];
    #pragma unroll
    for (int i = 0; i < 4; i++)
        #pragma unroll
        for (int j = 0; j < 4; j++) o[i][j] = 0.f;

    #pragma unroll 4
    for (int r = 0; r < RP; r++) {
        float p[4];
        #pragma unroll
        for (int i = 0; i < 4; i++) p[i] = Ps[(ty * 4 + i) * 260 + r];
        float4 v = *(float4*)&vps[r * DH + tx * 4];
        #pragma unroll
        for (int i = 0; i < 4; i++) {
            o[i][0] = fmaf(p[i], v.x, o[i][0]);
            o[i][1] = fmaf(p[i], v.y, o[i][1]);
            o[i][2] = fmaf(p[i], v.z, o[i][2]);
            o[i][3] = fmaf(p[i], v.w, o[i][3]);
        }
    }

    // ---- write AO[b, n, h*64 + d] (merge heads) ----
    const int b = bh >> 3, h = bh & 7;
    float* ao = g_AO + (b * NSEQ + n0) * DM + h * DH;
    #pragma unroll
    for (int i = 0; i < 4; i++) {
        float4 v = make_float4(o[i][0], o[i][1], o[i][2], o[i][3]);
        *(float4*)&ao[(ty * 4 + i) * DM + tx * 4] = v;
    }
}

// =====================================================================
// Kernel 4: output projection.  out = AO @ w_out + b_out
// grid (4, 256).  Same tiling as kernel 1; direct [m, c] output.
// =====================================================================
__global__ __launch_bounds__(256) void outproj_kernel(
    const float* __restrict__ wo, const float* __restrict__ bo,
    float* __restrict__ out)
{
    __shared__ float As[16][128];
    __shared__ float Bs[16][128];

    const int m0 = blockIdx.y * 128;
    const int n0 = blockIdx.x * 128;
    const int tid = threadIdx.x;
    const int tx = tid & 15, ty = tid >> 4;

    float acc[8][8];
    #pragma unroll
    for (int i = 0; i < 8; i++)
        #pragma unroll
        for (int j = 0; j < 8; j++) acc[i][j] = 0.f;

    for (int k0 = 0; k0 < DM; k0 += 16) {
        #pragma unroll
        for (int l = 0; l < 2; l++) {
            int s = l * 256 + tid;
            int row = s >> 2, kq = (s & 3) * 4;
            float4 v = *(const float4*)&g_AO[(m0 + row) * DM + k0 + kq];
            As[kq + 0][row] = v.x; As[kq + 1][row] = v.y;
            As[kq + 2][row] = v.z; As[kq + 3][row] = v.w;
        }
        #pragma unroll
        for (int l = 0; l < 2; l++) {
            int s = l * 256 + tid;
            int row = s >> 5, cq = (s & 31) * 4;
            *(float4*)&Bs[row][cq] = *(const float4*)&wo[(k0 + row) * DM + n0 + cq];
        }
        __syncthreads();
        #pragma unroll
        for (int kk = 0; kk < 16; kk++) {
            float a[8], b[8];
            *(float4*)&a[0] = *(float4*)&As[kk][ty * 8];
            *(float4*)&a[4] = *(float4*)&As[kk][ty * 8 + 4];
            *(float4*)&b[0] = *(float4*)&Bs[kk][tx * 8];
            *(float4*)&b[4] = *(float4*)&Bs[kk][tx * 8 + 4];
            #pragma unroll
            for (int i = 0; i < 8; i++)
                #pragma unroll
                for (int j = 0; j < 8; j++)
                    acc[i][j] = fmaf(a[i], b[j], acc[i][j]);
        }
        __syncthreads();
    }

    float4 bias0 = *(const float4*)&bo[n0 + tx * 8];
    float4 bias1 = *(const float4*)&bo[n0 + tx * 8 + 4];
    #pragma unroll
    for (int i = 0; i < 8; i++) {
        int m = m0 + ty * 8 + i;
        float4 v0 = make_float4(acc[i][0] + bias0.x, acc[i][1] + bias0.y,
                                acc[i][2] + bias0.z, acc[i][3] + bias0.w);
        float4 v1 = make_float4(acc[i][4] + bias1.x, acc[i][5] + bias1.y,
                                acc[i][6] + bias1.z, acc[i][7] + bias1.w);
        *(float4*)&out[m * DM + n0 + tx * 8]     = v0;
        *(float4*)&out[m * DM + n0 + tx * 8 + 4] = v1;
    }
}

// =====================================================================
extern "C" void kernel_launch(void* const* d_in, const int* in_sizes, int n_in,
                              void* d_out, int out_size)
{
    (void)in_sizes; (void)n_in; (void)out_size;
    const float* x  = (const float*)d_in[0];
    const float* wq = (const float*)d_in[1];
    const float* wk = (const float*)d_in[2];
    const float* wv = (const float*)d_in[3];
    const float* E  = (const float*)d_in[4];
    const float* F  = (const float*)d_in[5];
    const float* wo = (const float*)d_in[6];
    const float* bo = (const float*)d_in[7];
    float* out = (float*)d_out;

    cudaFuncSetAttribute(attn_kernel,
                         cudaFuncAttributeMaxDynamicSharedMemorySize,
                         ATTN_SMEM_BYTES);

    qkv_kernel<<<dim3(4, 256, 3), 256>>>(x, wq, wk, wv);
    proj_kernel<<<dim3(2, 64, 2), 256>>>(E, F);
    attn_kernel<<<dim3(64, 64), 256, ATTN_SMEM_BYTES>>>();
    outproj_kernel<<<dim3(4, 256), 256>>>(wo, bo, out);
}

// round 2
// speedup vs baseline: 3.4634x; 3.4634x over previous
#include <cuda_runtime.h>

#define BATCH 8
#define HEADS 8
#define NSEQ  4096
#define DM    512
#define DH    64
#define RP    256

// ---------------- scratch ----------------
__device__ float g_Q [BATCH*HEADS*NSEQ*DH];
__device__ float g_K [BATCH*HEADS*NSEQ*DH];
__device__ float g_V [BATCH*HEADS*NSEQ*DH];
__device__ float g_KP[BATCH*HEADS*RP*DH];
__device__ float g_VP[BATCH*HEADS*RP*DH];
__device__ float g_AO[BATCH*NSEQ*DM];

// ---------------- helpers ----------------
__device__ __forceinline__ float f2tf(float f) {
    unsigned u; asm("cvt.rna.tf32.f32 %0, %1;" : "=r"(u) : "f"(f));
    return __uint_as_float(u);
}
__device__ __forceinline__ float4 cvt4(float4 v) {
    return make_float4(f2tf(v.x), f2tf(v.y), f2tf(v.z), f2tf(v.w));
}
// D = A(16x8,row) * B(8x8,col) + D, tf32 inputs (as f32 bit patterns), f32 accum
__device__ __forceinline__ void mma_tf32(float c[4], float a0, float a1, float a2, float a3,
                                         float b0, float b1) {
    asm volatile(
        "mma.sync.aligned.m16n8k8.row.col.f32.tf32.tf32.f32 "
        "{%0,%1,%2,%3},{%4,%5,%6,%7},{%8,%9},{%0,%1,%2,%3};\n"
        : "+f"(c[0]), "+f"(c[1]), "+f"(c[2]), "+f"(c[3])
        : "r"(__float_as_uint(a0)), "r"(__float_as_uint(a1)),
          "r"(__float_as_uint(a2)), "r"(__float_as_uint(a3)),
          "r"(__float_as_uint(b0)), "r"(__float_as_uint(b1)));
}

// =====================================================================
// Kernel 1: QKV.  C[m,c] = sum_k x[m,k] w[k,c], head-split output.
// BM=128 BN=128 BK=32, double-buffered, 8 warps (2x4 -> warp 32x64).
// As: [m][36] (stride 36 == 4 mod 8 -> conflict-free A frags)
// Bs: [k][136] (stride 136 == 8 mod 32 -> conflict-free B frags)
// =====================================================================
#define QKV_AS (128*36)
#define QKV_BS (32*136)
#define QKV_SMEM ((2*QKV_AS + 2*QKV_BS)*4)

__global__ __launch_bounds__(256) void qkv_kernel(
    const float* __restrict__ x, const float* __restrict__ wq,
    const float* __restrict__ wk, const float* __restrict__ wv)
{
    extern __shared__ float sm[];
    float* As = sm;              // [2][128][36]
    float* Bs = sm + 2*QKV_AS;   // [2][32][136]

    const float* w; float* outp;
    if (blockIdx.z == 0)      { w = wq; outp = g_Q; }
    else if (blockIdx.z == 1) { w = wk; outp = g_K; }
    else                      { w = wv; outp = g_V; }

    const int m0 = blockIdx.y * 128, n0 = blockIdx.x * 128;
    const int tid = threadIdx.x;
    const int wid = tid >> 5, lane = tid & 31, g = lane >> 2, tig = lane & 3;
    const int wm = (wid >> 1) * 32, wn = (wid & 1) * 64;

    const int arow = tid >> 3, acol = (tid & 7) * 4;   // A loader
    const int brow = tid >> 5, bcol = (tid & 31) * 4;  // B loader

    float acc[2][8][4] = {};

    // prologue
    #pragma unroll
    for (int l = 0; l < 4; l++) {
        int r = l * 32 + arow;
        float4 v = *(const float4*)&x[(m0 + r) * DM + acol];
        *(float4*)&As[r * 36 + acol] = cvt4(v);
    }
    #pragma unroll
    for (int l = 0; l < 4; l++) {
        int r = l * 8 + brow;
        float4 v = *(const float4*)&w[r * DM + n0 + bcol];
        *(float4*)&Bs[r * 136 + bcol] = cvt4(v);
    }
    __syncthreads();

    for (int s = 0; s < 16; s++) {
        const int cur = s & 1;
        float4 la[4], lb[4];
        const bool pre = (s + 1 < 16);
        if (pre) {
            int k0 = (s + 1) * 32;
            #pragma unroll
            for (int l = 0; l < 4; l++)
                la[l] = *(const float4*)&x[(m0 + l * 32 + arow) * DM + k0 + acol];
            #pragma unroll
            for (int l = 0; l < 4; l++)
                lb[l] = *(const float4*)&w[(k0 + l * 8 + brow) * DM + n0 + bcol];
        }
        const float* A = As + cur * QKV_AS;
        const float* B = Bs + cur * QKV_BS;
        #pragma unroll
        for (int ks = 0; ks < 4; ks++) {
            int kb = ks * 8;
            float a[2][4];
            #pragma unroll
            for (int mt = 0; mt < 2; mt++) {
                int r = wm + mt * 16;
                a[mt][0] = A[(r + g)     * 36 + kb + tig];
                a[mt][1] = A[(r + g + 8) * 36 + kb + tig];
                a[mt][2] = A[(r + g)     * 36 + kb + tig + 4];
                a[mt][3] = A[(r + g + 8) * 36 + kb + tig + 4];
            }
            #pragma unroll
            for (int nt = 0; nt < 8; nt++) {
                float b0 = B[(kb + tig)     * 136 + wn + nt * 8 + g];
                float b1 = B[(kb + tig + 4) * 136 + wn + nt * 8 + g];
                #pragma unroll
                for (int mt = 0; mt < 2; mt++)
                    mma_tf32(acc[mt][nt], a[mt][0], a[mt][1], a[mt][2], a[mt][3], b0, b1);
            }
        }
        if (pre) {
            const int nb = (s + 1) & 1;
            #pragma unroll
            for (int l = 0; l < 4; l++)
                *(float4*)&As[nb * QKV_AS + (l * 32 + arow) * 36 + acol] = cvt4(la[l]);
            #pragma unroll
            for (int l = 0; l < 4; l++)
                *(float4*)&Bs[nb * QKV_BS + (l * 8 + brow) * 136 + bcol] = cvt4(lb[l]);
        }
        __syncthreads();
    }

    // epilogue (head-split)
    #pragma unroll
    for (int mt = 0; mt < 2; mt++) {
        #pragma unroll
        for (int i = 0; i < 2; i++) {
            int m = m0 + wm + mt * 16 + g + i * 8;
            int bb = m >> 12, ns = m & (NSEQ - 1);
            #pragma unroll
            for (int nt = 0; nt < 8; nt++) {
                int c = n0 + wn + nt * 8 + tig * 2;
                int h = c >> 6, dh = c & 63;
                *(float2*)&outp[((bb * HEADS + h) * NSEQ + ns) * DH + dh] =
                    make_float2(acc[mt][nt][i * 2], acc[mt][nt][i * 2 + 1]);
            }
        }
    }
}

// =====================================================================
// Kernel 2: low-rank proj.  KP[r,d] = sum_n E[n,r] K[n,d]  (per b,h)
// BM=128(r) BN=64(d) BK=32, K=4096, double-buffered.
// As: [k][136] (natural: E rows are m-contiguous). Bs: [k][72].
// 8 warps 2x4... actually 4x2 -> warp 32x32.
// =====================================================================
#define PRJ_AS (32*136)
#define PRJ_BS (32*72)
#define PRJ_SMEM ((2*PRJ_AS + 2*PRJ_BS)*4)

__global__ __launch_bounds__(256) void proj_kernel(
    const float* __restrict__ E, const float* __restrict__ F)
{
    extern __shared__ float sm[];
    float* As = sm;
    float* Bs = sm + 2*PRJ_AS;

    const int bh = blockIdx.y, h = bh & 7;
    const int r0 = blockIdx.x * 128;
    const float* P = (blockIdx.z == 0 ? E : F) + h * NSEQ * RP;
    const float* S = (blockIdx.z == 0 ? g_K : g_V) + bh * NSEQ * DH;
    float*       D = (blockIdx.z == 0 ? g_KP : g_VP) + bh * RP * DH;

    const int tid = threadIdx.x;
    const int wid = tid >> 5, lane = tid & 31, g = lane >> 2, tig = lane & 3;
    const int wm = (wid >> 1) * 32, wn = (wid & 1) * 32;

    const int arow = tid >> 5, acol = (tid & 31) * 4;  // A: 32 rows x 32 f4
    const int brow = tid >> 4, bcol = (tid & 15) * 4;  // B: 32 rows x 16 f4

    float acc[2][4][4] = {};

    #pragma unroll
    for (int l = 0; l < 4; l++) {
        int r = l * 8 + arow;
        float4 v = *(const float4*)&P[r * RP + r0 + acol];
        *(float4*)&As[r * 136 + acol] = cvt4(v);
    }
    #pragma unroll
    for (int l = 0; l < 2; l++) {
        int r = l * 16 + brow;
        float4 v = *(const float4*)&S[r * DH + bcol];
        *(float4*)&Bs[r * 72 + bcol] = cvt4(v);
    }
    __syncthreads();

    const int NST = NSEQ / 32;  // 128 stages
    for (int s = 0; s < NST; s++) {
        const int cur = s & 1;
        float4 la[4], lb[2];
        const bool pre = (s + 1 < NST);
        if (pre) {
            int k0 = (s + 1) * 32;
            #pragma unroll
            for (int l = 0; l < 4; l++)
                la[l] = *(const float4*)&P[(k0 + l * 8 + arow) * RP + r0 + acol];
            #pragma unroll
            for (int l = 0; l < 2; l++)
                lb[l] = *(const float4*)&S[(k0 + l * 16 + brow) * DH + bcol];
        }
        const float* A = As + cur * PRJ_AS;
        const float* B = Bs + cur * PRJ_BS;
        #pragma unroll
        for (int ks = 0; ks < 4; ks++) {
            int kb = ks * 8;
            float a[2][4];
            #pragma unroll
            for (int mt = 0; mt < 2; mt++) {
                int r = wm + mt * 16;
                a[mt][0] = A[(kb + tig)     * 136 + r + g];
                a[mt][1] = A[(kb + tig)     * 136 + r + g + 8];
                a[mt][2] = A[(kb + tig + 4) * 136 + r + g];
                a[mt][3] = A[(kb + tig + 4) * 136 + r + g + 8];
            }
            #pragma unroll
            for (int nt = 0; nt < 4; nt++) {
                float b0 = B[(kb + tig)     * 72 + wn + nt * 8 + g];
                float b1 = B[(kb + tig + 4) * 72 + wn + nt * 8 + g];
                #pragma unroll
                for (int mt = 0; mt < 2; mt++)
                    mma_tf32(acc[mt][nt], a[mt][0], a[mt][1], a[mt][2], a[mt][3], b0, b1);
            }
        }
        if (pre) {
            const int nb = (s + 1) & 1;
            #pragma unroll
            for (int l = 0; l < 4; l++)
                *(float4*)&As[nb * PRJ_AS + (l * 8 + arow) * 136 + acol] = cvt4(la[l]);
            #pragma unroll
            for (int l = 0; l < 2; l++)
                *(float4*)&Bs[nb * PRJ_BS + (l * 16 + brow) * 72 + bcol] = cvt4(lb[l]);
        }
        __syncthreads();
    }

    #pragma unroll
    for (int mt = 0; mt < 2; mt++) {
        #pragma unroll
        for (int i = 0; i < 2; i++) {
            int r = r0 + wm + mt * 16 + g + i * 8;
            #pragma unroll
            for (int nt = 0; nt < 4; nt++) {
                int c = wn + nt * 8 + tig * 2;
                *(float2*)&D[r * DH + c] =
                    make_float2(acc[mt][nt][i * 2], acc[mt][nt][i * 2 + 1]);
            }
        }
    }
}

// =====================================================================
// Kernel 3: fused attention, persistent kp/vp.
// grid (8, 64): block loads kp/vp once, loops 8 chunks of 64 Q rows.
// phase1: S = Q @ kp^T (mma), softmax stats via shfl + smem,
// P (tf32) -> smem, phase2: O = P @ vp (mma), /rowsum in epilogue.
// =====================================================================
#define AT_QS (64*68)
#define AT_KP (256*68)
#define AT_VP (256*72)
#define AT_PS (64*260)
#define AT_SMEM ((AT_QS + AT_KP + AT_VP + AT_PS + 256 + 64)*4)

__global__ __launch_bounds__(256) void attn_kernel()
{
    extern __shared__ float sm[];
    float* Qs   = sm;
    float* kps  = Qs + AT_QS;      // [256][68]  (r, d)
    float* vps  = kps + AT_KP;     // [256][72]  (r, d)
    float* Ps   = vps + AT_VP;     // [64][260]
    float* redM = Ps + AT_PS;      // [64][2]
    float* redS = redM + 128;      // [64][2]

    const int bh = blockIdx.y;
    const float* kp = g_KP + bh * RP * DH;
    const float* vp = g_VP + bh * RP * DH;

    const int tid = threadIdx.x;
    const int wid = tid >> 5, lane = tid & 31, g = lane >> 2, tig = lane & 3;
    const int wm = (wid >> 1) * 16, wn = wid & 1;

    // persistent tiles
    #pragma unroll
    for (int l = 0; l < 16; l++) {
        int idx = l * 256 + tid;
        int r = idx >> 4, c = (idx & 15) * 4;
        *(float4*)&kps[r * 68 + c] = cvt4(*(const float4*)&kp[r * DH + c]);
        *(float4*)&vps[r * 72 + c] = cvt4(*(const float4*)&vp[r * DH + c]);
    }

    const int b = bh >> 3, h = bh & 7;
    const float scale = 0.125f;  // 1/sqrt(64)

    for (int ci = 0; ci < 8; ci++) {
        const int n0 = blockIdx.x * 512 + ci * 64;
        const float* Qg = g_Q + (bh * NSEQ + n0) * DH;

        __syncthreads();  // prev-iter Ps reads done; kp/vp visible (iter 0)
        #pragma unroll
        for (int l = 0; l < 4; l++) {
            int idx = l * 256 + tid;
            int r = idx >> 4, c = (idx & 15) * 4;
            *(float4*)&Qs[r * 68 + c] = cvt4(*(const float4*)&Qg[r * DH + c]);
        }
        __syncthreads();

        // ---- phase 1: S = Q @ kp^T.  warp = 16 rows x 128 cols ----
        float acc[16][4] = {};
        #pragma unroll
        for (int ks = 0; ks < 8; ks++) {
            int kb = ks * 8;
            float a0 = Qs[(wm + g)     * 68 + kb + tig];
            float a1 = Qs[(wm + g + 8) * 68 + kb + tig];
            float a2 = Qs[(wm + g)     * 68 + kb + tig + 4];
            float a3 = Qs[(wm + g + 8) * 68 + kb + tig + 4];
            #pragma unroll
            for (int nt = 0; nt < 16; nt++) {
                int rr = wn * 128 + nt * 8 + g;
                float b0 = kps[rr * 68 + kb + tig];
                float b1 = kps[rr * 68 + kb + tig + 4];
                mma_tf32(acc[nt], a0, a1, a2, a3, b0, b1);
            }
        }

        // ---- softmax stats ----
        const int r0 = wm + g, r1 = r0 + 8;
        float mx0 = -1e30f, mx1 = -1e30f;
        #pragma unroll
        for (int nt = 0; nt < 16; nt++) {
            mx0 = fmaxf(mx0, fmaxf(acc[nt][0], acc[nt][1]));
            mx1 = fmaxf(mx1, fmaxf(acc[nt][2], acc[nt][3]));
        }
        mx0 = fmaxf(mx0, __shfl_xor_sync(0xffffffffu, mx0, 1));
        mx0 = fmaxf(mx0, __shfl_xor_sync(0xffffffffu, mx0, 2));
        mx1 = fmaxf(mx1, __shfl_xor_sync(0xffffffffu, mx1, 1));
        mx1 = fmaxf(mx1, __shfl_xor_sync(0xffffffffu, mx1, 2));
        if (tig == 0) { redM[r0 * 2 + wn] = mx0; redM[r1 * 2 + wn] = mx1; }
        __syncthreads();
        mx0 = fmaxf(redM[r0 * 2], redM[r0 * 2 + 1]) * scale;
        mx1 = fmaxf(redM[r1 * 2], redM[r1 * 2 + 1]) * scale;

        float s0 = 0.f, s1 = 0.f;
        #pragma unroll
        for (int nt = 0; nt < 16; nt++) {
            int c = wn * 128 + nt * 8 + tig * 2;
            float e0 = __expf(acc[nt][0] * scale - mx0);
            float e1 = __expf(acc[nt][1] * scale - mx0);
            s0 += e0 + e1;
            *(float2*)&Ps[r0 * 260 + c] = make_float2(f2tf(e0), f2tf(e1));
            float e2 = __expf(acc[nt][2] * scale - mx1);
            float e3 = __expf(acc[nt][3] * scale - mx1);
            s1 += e2 + e3;
            *(float2*)&Ps[r1 * 260 + c] = make_float2(f2tf(e2), f2tf(e3));
        }
        s0 += __shfl_xor_sync(0xffffffffu, s0, 1);
        s0 += __shfl_xor_sync(0xffffffffu, s0, 2);
        s1 += __shfl_xor_sync(0xffffffffu, s1, 1);
        s1 += __shfl_xor_sync(0xffffffffu, s1, 2);
        if (tig == 0) { redS[r0 * 2 + wn] = s0; redS[r1 * 2 + wn] = s1; }
        __syncthreads();  // Ps + redS ready

        // ---- phase 2: O = P @ vp.  warp = 16 rows x 32 cols ----
        float acc2[4][4] = {};
        #pragma unroll 8
        for (int ks = 0; ks < 32; ks++) {
            int kb = ks * 8;
            float a0 = Ps[(wm + g)     * 260 + kb + tig];
            float a1 = Ps[(wm + g + 8) * 260 + kb + tig];
            float a2 = Ps[(wm + g)     * 260 + kb + tig + 4];
            float a3 = Ps[(wm + g + 8) * 260 + kb + tig + 4];
            #pragma unroll
            for (int nt = 0; nt < 4; nt++) {
                int cc = wn * 32 + nt * 8 + g;
                float b0 = vps[(kb + tig)     * 72 + cc];
                float b1 = vps[(kb + tig + 4) * 72 + cc];
                mma_tf32(acc2[nt], a0, a1, a2, a3, b0, b1);
            }
        }

        const float inv0 = __frcp_rn(redS[r0 * 2] + redS[r0 * 2 + 1]);
        const float inv1 = __frcp_rn(redS[r1 * 2] + redS[r1 * 2 + 1]);
        float* ao = g_AO + (b * NSEQ + n0) * DM + h * DH;
        #pragma unroll
        for (int nt = 0; nt < 4; nt++) {
            int c = wn * 32 + nt * 8 + tig * 2;
            *(float2*)&ao[r0 * DM + c] = make_float2(acc2[nt][0] * inv0, acc2[nt][1] * inv0);
            *(float2*)&ao[r1 * DM + c] = make_float2(acc2[nt][2] * inv1, acc2[nt][3] * inv1);
        }
    }
}

// =====================================================================
// Kernel 4: out = AO @ w_out + b_out.  Same tiling as qkv.
// =====================================================================
__global__ __launch_bounds__(256) void outproj_kernel(
    const float* __restrict__ wo, const float* __restrict__ bo,
    float* __restrict__ out)
{
    extern __shared__ float sm[];
    float* As = sm;
    float* Bs = sm + 2*QKV_AS;

    const int m0 = blockIdx.y * 128, n0 = blockIdx.x * 128;
    const int tid = threadIdx.x;
    const int wid = tid >> 5, lane = tid & 31, g = lane >> 2, tig = lane & 3;
    const int wm = (wid >> 1) * 32, wn = (wid & 1) * 64;

    const int arow = tid >> 3, acol = (tid & 7) * 4;
    const int brow = tid >> 5, bcol = (tid & 31) * 4;

    float acc[2][8][4] = {};

    #pragma unroll
    for (int l = 0; l < 4; l++) {
        int r = l * 32 + arow;
        *(float4*)&As[r * 36 + acol] = cvt4(*(const float4*)&g_AO[(m0 + r) * DM + acol]);
    }
    #pragma unroll
    for (int l = 0; l < 4; l++) {
        int r = l * 8 + brow;
        *(float4*)&Bs[r * 136 + bcol] = cvt4(*(const float4*)&wo[r * DM + n0 + bcol]);
    }
    __syncthreads();

    for (int s = 0; s < 16; s++) {
        const int cur = s & 1;
        float4 la[4], lb[4];
        const bool pre = (s + 1 < 16);
        if (pre) {
            int k0 = (s + 1) * 32;
            #pragma unroll
            for (int l = 0; l < 4; l++)
                la[l] = *(const float4*)&g_AO[(m0 + l * 32 + arow) * DM + k0 + acol];
            #pragma unroll
            for (int l = 0; l < 4; l++)
                lb[l] = *(const float4*)&wo[(k0 + l * 8 + brow) * DM + n0 + bcol];
        }
        const float* A = As + cur * QKV_AS;
        const float* B = Bs + cur * QKV_BS;
        #pragma unroll
        for (int ks = 0; ks < 4; ks++) {
            int kb = ks * 8;
            float a[2][4];
            #pragma unroll
            for (int mt = 0; mt < 2; mt++) {
                int r = wm + mt * 16;
                a[mt][0] = A[(r + g)     * 36 + kb + tig];
                a[mt][1] = A[(r + g + 8) * 36 + kb + tig];
                a[mt][2] = A[(r + g)     * 36 + kb + tig + 4];
                a[mt][3] = A[(r + g + 8) * 36 + kb + tig + 4];
            }
            #pragma unroll
            for (int nt = 0; nt < 8; nt++) {
                float b0 = B[(kb + tig)     * 136 + wn + nt * 8 + g];
                float b1 = B[(kb + tig + 4) * 136 + wn + nt * 8 + g];
                #pragma unroll
                for (int mt = 0; mt < 2; mt++)
                    mma_tf32(acc[mt][nt], a[mt][0], a[mt][1], a[mt][2], a[mt][3], b0, b1);
            }
        }
        if (pre) {
            const int nb = (s + 1) & 1;
            #pragma unroll
            for (int l = 0; l < 4; l++)
                *(float4*)&As[nb * QKV_AS + (l * 32 + arow) * 36 + acol] = cvt4(la[l]);
            #pragma unroll
            for (int l = 0; l < 4; l++)
                *(float4*)&Bs[nb * QKV_BS + (l * 8 + brow) * 136 + bcol] = cvt4(lb[l]);
        }
        __syncthreads();
    }

    #pragma unroll
    for (int mt = 0; mt < 2; mt++) {
        #pragma unroll
        for (int i = 0; i < 2; i++) {
            int m = m0 + wm + mt * 16 + g + i * 8;
            #pragma unroll
            for (int nt = 0; nt < 8; nt++) {
                int c = n0 + wn + nt * 8 + tig * 2;
                float2 bias = *(const float2*)&bo[c];
                *(float2*)&out[m * DM + c] =
                    make_float2(acc[mt][nt][i * 2] + bias.x, acc[mt][nt][i * 2 + 1] + bias.y);
            }
        }
    }
}

// =====================================================================
extern "C" void kernel_launch(void* const* d_in, const int* in_sizes, int n_in,
                              void* d_out, int out_size)
{
    (void)in_sizes; (void)n_in; (void)out_size;
    const float* x  = (const float*)d_in[0];
    const float* wq = (const float*)d_in[1];
    const float* wk = (const float*)d_in[2];
    const float* wv = (const float*)d_in[3];
    const float* E  = (const float*)d_in[4];
    const float* F  = (const float*)d_in[5];
    const float* wo = (const float*)d_in[6];
    const float* bo = (const float*)d_in[7];
    float* out = (float*)d_out;

    cudaFuncSetAttribute(qkv_kernel,     cudaFuncAttributeMaxDynamicSharedMemorySize, QKV_SMEM);
    cudaFuncSetAttribute(proj_kernel,    cudaFuncAttributeMaxDynamicSharedMemorySize, PRJ_SMEM);
    cudaFuncSetAttribute(attn_kernel,    cudaFuncAttributeMaxDynamicSharedMemorySize, AT_SMEM);
    cudaFuncSetAttribute(outproj_kernel, cudaFuncAttributeMaxDynamicSharedMemorySize, QKV_SMEM);

    qkv_kernel    <<<dim3(4, 256, 3), 256, QKV_SMEM>>>(x, wq, wk, wv);
    proj_kernel   <<<dim3(2, 64, 2),  256, PRJ_SMEM>>>(E, F);
    attn_kernel   <<<dim3(8, 64),     256, AT_SMEM>>>();
    outproj_kernel<<<dim3(4, 256),    256, QKV_SMEM>>>(wo, bo, out);
}